// round 15
// baseline (speedup 1.0000x reference)
#include <cuda_runtime.h>
#include <cuda_fp16.h>
#include <math.h>

#define H2 2048
#define T_STEPS 2048
#define NG 8192            // 4*H2
#define LAYERS 4
#define JJ 14              // h-elements per CTA
#define ROWS 56            // 4*JJ gate rows per CTA
#define NCTA 147           // ceil(2048/14)
#define SCAN_THREADS 1024
#define SMEM_ROWS 55                      // rows kept in SMEM (row 55 streamed via L1)
#define SCAN_SMEM (SMEM_ROWS * H2 * 2)    // 225280 bytes of fp16 weights
#define HCOPIES 8                         // h replication factor

// ---------------- scratch (static device globals; no allocation) ----------------
__device__ float  g_xw[(size_t)T_STEPS * NG];        // 67 MB: xw for current layer
__device__ __align__(16) __half g_hseq[(size_t)T_STEPS * H2]; // h sequence (fp16)
// double-buffered, 8x-replicated h for the scan: copy c read only by CTAs with bid&7==c
__device__ __align__(16) __half g_hrep[2][HCOPIES][H2];
__device__ __align__(16) __half g_wext[(size_t)LAYERS * NCTA * H2]; // per-CTA extra row (fp16)
__device__ float  g_hlast[H2];                       // fp32 h at t=T-1
// single-hop barrier state: one counter per step (128B apart) + prologue counter.
// All counters are MONOTONE (+NCTA per scan launch, never reset); g_epoch counts
// completed scan launches. Target for launch E is (E+1)*NCTA. Graph-replay safe.
__device__ unsigned g_steps[T_STEPS * 32];
__device__ unsigned g_zcnt[32];
__device__ unsigned g_epoch = 0;

// ---------------- helpers ----------------
static __device__ __forceinline__ float2 h2_to_f2(unsigned u) {
    __half2 h;
    *reinterpret_cast<unsigned*>(&h) = u;
    return __half22float2(h);
}
static __device__ __forceinline__ __half2 u2h2(unsigned u) {
    __half2 h;
    *reinterpret_cast<unsigned*>(&h) = u;
    return h;
}
static __device__ __forceinline__ uint4 ldcg_v4(const uint4* p) {
    uint4 v;
    asm volatile("ld.global.cg.v4.u32 {%0,%1,%2,%3}, [%4];"
                 : "=r"(v.x), "=r"(v.y), "=r"(v.z), "=r"(v.w) : "l"(p));
    return v;
}
static __device__ __forceinline__ unsigned ld_cg_u32(const unsigned* p) {
    unsigned v;
    asm volatile("ld.global.cg.u32 %0, [%1];" : "=r"(v) : "l"(p));
    return v;
}
// scoped memory-model ops: no full MEMBAR anywhere in the sync path
static __device__ __forceinline__ void red_add_release(unsigned* p) {
    asm volatile("red.release.gpu.global.add.u32 [%0], 1;" :: "l"(p) : "memory");
}
static __device__ __forceinline__ unsigned ld_acq(const unsigned* p) {
    unsigned v;
    asm volatile("ld.acquire.gpu.global.u32 %0, [%1];" : "=r"(v) : "l"(p) : "memory");
    return v;
}
static __device__ __forceinline__ void st_rlx(unsigned* p, unsigned v) {
    asm volatile("st.relaxed.gpu.global.u32 [%0], %1;" :: "l"(p), "r"(v) : "memory");
}
static __device__ __forceinline__ float sigmoidf_fast(float x) {
    return 1.0f / (1.0f + __expf(-x));
}
static __device__ __forceinline__ float tanhf_fast(float x) {
    return 2.0f / (1.0f + __expf(-2.0f * x)) - 1.0f;
}

// arrive+wait barrier used only in the prologue (thread 0)
static __device__ __forceinline__ void step_bar(unsigned* cnt, unsigned target) {
    red_add_release(cnt);
    int spin = 0;
    while ((int)(ld_acq(cnt) - target) < 0) { if (++spin > 64) __nanosleep(64); }
}

// ---------------- pack per-CTA extra weight row (gate o, jl=13) to fp16 ----------------
__global__ void pack_extra(const float* __restrict__ whh) {
    int k = blockIdx.x;          // CTA index
    int l = blockIdx.y;          // layer
    int j = JJ * k + JJ - 1;     // h index of the extra row
    __half* dst = g_wext + ((size_t)l * NCTA + k) * H2;
    if (j >= H2) {
        for (int i = threadIdx.x; i < H2; i += 256) dst[i] = __float2half(0.0f);
        return;
    }
    const float* src = whh + ((size_t)l * NG + 3 * H2 + j) * H2;
    for (int i = threadIdx.x; i < H2; i += 256) dst[i] = __float2half_rn(src[i]);
}

// ---------------- nop pad so lstm_scan(layer1) lands on ncu's -s 5 capture slot ----
__global__ void nop_kernel() {}

// ---------------- layer-0 xw: xw[t][r] = event[t]*w_ih0[r] + b_ih[r] + b_hh[r] ----------------
__global__ void xw0_kernel(const float* __restrict__ event, const float* __restrict__ w0,
                           const float* __restrict__ bih, const float* __restrict__ bhh) {
    int t = blockIdx.y;
    int c = (blockIdx.x * blockDim.x + threadIdx.x) * 4;
    float e = event[t];
    float4 w  = *(const float4*)(w0 + c);
    float4 bi = *(const float4*)(bih + c);
    float4 bh = *(const float4*)(bhh + c);
    float4 r;
    r.x = fmaf(e, w.x, bi.x + bh.x);
    r.y = fmaf(e, w.y, bi.y + bh.y);
    r.z = fmaf(e, w.z, bi.z + bh.z);
    r.w = fmaf(e, w.w, bi.w + bh.w);
    *(float4*)(g_xw + (size_t)t * NG + c) = r;
}

// ---------------- xw GEMM: g_xw[t][r] = sum_k g_hseq[t][k] * B[r][k] + bias[r] ----------------
#define BM 128
#define BN 128
#define BK 32
#define SPAD 4

__global__ __launch_bounds__(256, 2) void gemm_xw(const float* __restrict__ B,
                                                  const float* __restrict__ bih,
                                                  const float* __restrict__ bhh) {
    __shared__ float As[BK][BM + SPAD];
    __shared__ float Bs[BK][BN + SPAD];
    const int tid = threadIdx.x;
    const int tx = tid & 15;
    const int ty = tid >> 4;
    const int row0 = blockIdx.y * BM;   // t
    const int col0 = blockIdx.x * BN;   // r

    const int lr = tid >> 1;            // 0..127 (tile row for loads)
    const int lc = (tid & 1) * 16;      // 0 or 16 (k offset for loads)
    const __half* aptr = g_hseq + (size_t)(row0 + lr) * H2 + lc;
    const float*  bptr = B      + (size_t)(col0 + lr) * H2 + lc;

    float acc[8][8];
#pragma unroll
    for (int i = 0; i < 8; i++)
#pragma unroll
        for (int j = 0; j < 8; j++) acc[i][j] = 0.0f;

    for (int k0 = 0; k0 < H2; k0 += BK) {
        uint4 a0 = *(const uint4*)(aptr + k0);
        uint4 a1 = *(const uint4*)(aptr + k0 + 8);
        float4 b0 = *(const float4*)(bptr + k0);
        float4 b1 = *(const float4*)(bptr + k0 + 4);
        float4 b2 = *(const float4*)(bptr + k0 + 8);
        float4 b3 = *(const float4*)(bptr + k0 + 12);
        __syncthreads();
        {
            unsigned aw[8] = {a0.x, a0.y, a0.z, a0.w, a1.x, a1.y, a1.z, a1.w};
#pragma unroll
            for (int e = 0; e < 8; e++) {
                float2 f = h2_to_f2(aw[e]);
                As[lc + 2 * e][lr]     = f.x;
                As[lc + 2 * e + 1][lr] = f.y;
            }
            float bw[16] = {b0.x, b0.y, b0.z, b0.w, b1.x, b1.y, b1.z, b1.w,
                            b2.x, b2.y, b2.z, b2.w, b3.x, b3.y, b3.z, b3.w};
#pragma unroll
            for (int e = 0; e < 16; e++) Bs[lc + e][lr] = bw[e];
        }
        __syncthreads();
#pragma unroll
        for (int k = 0; k < BK; k++) {
            float4 xa = *(const float4*)&As[k][ty * 8];
            float4 xb = *(const float4*)&As[k][ty * 8 + 4];
            float4 ya = *(const float4*)&Bs[k][tx * 8];
            float4 yb = *(const float4*)&Bs[k][tx * 8 + 4];
            float av[8] = {xa.x, xa.y, xa.z, xa.w, xb.x, xb.y, xb.z, xb.w};
            float bv[8] = {ya.x, ya.y, ya.z, ya.w, yb.x, yb.y, yb.z, yb.w};
#pragma unroll
            for (int i = 0; i < 8; i++)
#pragma unroll
                for (int j = 0; j < 8; j++) acc[i][j] = fmaf(av[i], bv[j], acc[i][j]);
        }
    }

    float bias[8];
#pragma unroll
    for (int j = 0; j < 8; j++) {
        int c = col0 + tx * 8 + j;
        bias[j] = __ldg(bih + c) + __ldg(bhh + c);
    }
#pragma unroll
    for (int i = 0; i < 8; i++) {
        float* crow = g_xw + (size_t)(row0 + ty * 8 + i) * NG + col0 + tx * 8;
        float4 v0 = {acc[i][0] + bias[0], acc[i][1] + bias[1], acc[i][2] + bias[2], acc[i][3] + bias[3]};
        float4 v1 = {acc[i][4] + bias[4], acc[i][5] + bias[5], acc[i][6] + bias[6], acc[i][7] + bias[7]};
        *(float4*)crow = v0;
        *(float4*)(crow + 4) = v1;
    }
}

// ---------------- persistent LSTM scan (v7) ------------------------------------
// 32 warps: warp = grp + 8*kq over K-quarter kq. Single interleaved reduction
// tail (7 rows x 2 half2 accs). Combine replicated across warps 0-7 (identical
// deterministic math; each publishes one h copy; cst double-buffered). Warp 0
// arrives fire-and-forget after bar.sync(1,256); warp 8 polls the step counter
// concurrently with the combine; block __syncthreads joins everyone.
__global__ __launch_bounds__(SCAN_THREADS, 1) void lstm_scan(const float* __restrict__ whh,
                                                             int layer) {
    extern __shared__ __align__(16) unsigned char smem_raw[];
    __half2* wsh = (__half2*)smem_raw;          // SMEM_ROWS x 1024 half2
    __shared__ __align__(16) uint4 h_s[256];    // staged h_{t-1} (4KB)
    __shared__ float gpart[4][ROWS];
    __shared__ float cst[2][JJ];                // double-buffered cell state
    __shared__ unsigned s_tgt;

    const int tid  = threadIdx.x;
    const int lane = tid & 31;
    const int warp = tid >> 5;
    const int grp  = warp & 7;
    const int kq   = warp >> 3;                 // 0..3
    const int koff = kq * 64;                   // uint4 offset into a 256-uint4 row
    const int j0   = blockIdx.x * JJ;
    const int nj   = (H2 - j0 < JJ) ? (H2 - j0) : JJ;
    const int last_layer = (layer == LAYERS - 1);
    const bool cta0 = (blockIdx.x == 0);

    // launch target: all barrier counters gain +NCTA per scan launch (monotone)
    unsigned E = 0;
    if (tid == 0) {
        E = ld_cg_u32(&g_epoch);
        s_tgt = (E + 1) * (unsigned)NCTA;
    }

    // zero this CTA's h slots in all copies of both scan buffers
    if (tid < JJ) {
        int j = j0 + tid;
        if (j < H2) {
            __half z = __float2half(0.0f);
#pragma unroll
            for (int c = 0; c < HCOPIES; c++) {
                g_hrep[0][c][j] = z;
                g_hrep[1][c][j] = z;
            }
        }
    }

    // load + convert this CTA's first 55 weight rows into SMEM (row r = gate*JJ + jl)
    for (int r = warp; r < SMEM_ROWS; r += 32) {
        int gate = r / JJ;
        int jl = r - gate * JJ;
        __half2* dst = wsh + r * (H2 / 2);
        if (jl < nj) {
            const float2* src = (const float2*)(whh + ((size_t)gate * H2 + j0 + jl) * H2);
            for (int p = lane; p < H2 / 2; p += 32) {
                float2 v = __ldg(src + p);
                dst[p] = __floats2half2_rn(v.x, v.y);
            }
        } else {
            for (int p = lane; p < H2 / 2; p += 32) dst[p] = __half2half2(__float2half(0.0f));
        }
    }
    if (tid < JJ) { cst[0][tid] = 0.0f; cst[1][tid] = 0.0f; }
    __syncthreads();
    const unsigned tgt = s_tgt;

    // prologue barrier: zeroed h slots visible grid-wide
    if (tid == 0) step_bar(&g_zcnt[0], tgt);
    __syncthreads();

    const uint4* wbase = (const uint4*)smem_raw;
    const uint4* wext  = (const uint4*)(g_wext + ((size_t)layer * NCTA + blockIdx.x) * H2);
    const int mycpy = blockIdx.x & (HCOPIES - 1);

    for (int t = 0; t < T_STEPS; ++t) {
        // stage h_{t-1} from this CTA's copy: one 16B .cg load per 16B (256 threads)
        if (tid < 256) {
            h_s[tid] = ldcg_v4(((const uint4*)(&g_hrep[t & 1][mycpy][0])) + tid);
        }
        // prefetch xw for this CTA's gate entries (combine warps 0-7, per-warp copy)
        float xwi = 0.f, xwf = 0.f, xwg = 0.f, xwo = 0.f;
        if (warp < 8 && lane < nj) {
            const float* xwt = g_xw + (size_t)t * NG + j0 + lane;
            xwi = __ldg(xwt);
            xwf = __ldg(xwt + H2);
            xwg = __ldg(xwt + 2 * H2);
            xwo = __ldg(xwt + 3 * H2);
        }
        __syncthreads();   // h_s ready

        // this warp's K-quarter of h: 8 half2 regs (broadcast across same-kq warps)
        uint4 hu0 = h_s[koff + lane];
        uint4 hu1 = h_s[koff + lane + 32];
        __half2 hh[8];
        hh[0]=u2h2(hu0.x); hh[1]=u2h2(hu0.y); hh[2]=u2h2(hu0.z); hh[3]=u2h2(hu0.w);
        hh[4]=u2h2(hu1.x); hh[5]=u2h2(hu1.y); hh[6]=u2h2(hu1.z); hh[7]=u2h2(hu1.w);

        // 7 rows, 2 independent half2 accumulators each; single interleaved tail
        __half2 acc0[7], acc1[7];
#pragma unroll
        for (int rr = 0; rr < 7; rr++) {
            const uint4* wr = (rr == 6 && grp == 7) ? (wext + koff)
                                                    : (wbase + (size_t)(grp * 7 + rr) * 256 + koff);
            uint4 wv0 = wr[lane];
            uint4 wv1 = wr[lane + 32];
            __half2 a0 = __hmul2(u2h2(wv0.x), hh[0]);
            __half2 a1 = __hmul2(u2h2(wv0.y), hh[1]);
            a0 = __hfma2(u2h2(wv0.z), hh[2], a0);
            a1 = __hfma2(u2h2(wv0.w), hh[3], a1);
            a0 = __hfma2(u2h2(wv1.x), hh[4], a0);
            a1 = __hfma2(u2h2(wv1.y), hh[5], a1);
            a0 = __hfma2(u2h2(wv1.z), hh[6], a0);
            a1 = __hfma2(u2h2(wv1.w), hh[7], a1);
            acc0[rr] = a0; acc1[rr] = a1;
        }
        float ared[7];
#pragma unroll
        for (int rr = 0; rr < 7; rr++) {
            __half2 s = __hadd2(acc0[rr], acc1[rr]);
            float2 f = __half22float2(s);
            ared[rr] = f.x + f.y;
        }
#pragma unroll
        for (int o = 16; o; o >>= 1) {
            ared[0] += __shfl_xor_sync(0xffffffffu, ared[0], o);
            ared[1] += __shfl_xor_sync(0xffffffffu, ared[1], o);
            ared[2] += __shfl_xor_sync(0xffffffffu, ared[2], o);
            ared[3] += __shfl_xor_sync(0xffffffffu, ared[3], o);
            ared[4] += __shfl_xor_sync(0xffffffffu, ared[4], o);
            ared[5] += __shfl_xor_sync(0xffffffffu, ared[5], o);
            ared[6] += __shfl_xor_sync(0xffffffffu, ared[6], o);
        }
        if (lane == 0) {
#pragma unroll
            for (int rr = 0; rr < 7; rr++) gpart[kq][grp * 7 + rr] = ared[rr];
        }
        __syncthreads();

        // redundant combine in warps 0-7 (identical math); each publishes 1 copy.
        // warp 8 polls the step counter concurrently; block sync joins all.
        if (warp < 8) {
            if (lane < nj) {
                int jl = lane;
                float gi = (gpart[0][0*JJ+jl] + gpart[1][0*JJ+jl]) + (gpart[2][0*JJ+jl] + gpart[3][0*JJ+jl]) + xwi;
                float gf = (gpart[0][1*JJ+jl] + gpart[1][1*JJ+jl]) + (gpart[2][1*JJ+jl] + gpart[3][1*JJ+jl]) + xwf;
                float gg = (gpart[0][2*JJ+jl] + gpart[1][2*JJ+jl]) + (gpart[2][2*JJ+jl] + gpart[3][2*JJ+jl]) + xwg;
                float go = (gpart[0][3*JJ+jl] + gpart[1][3*JJ+jl]) + (gpart[2][3*JJ+jl] + gpart[3][3*JJ+jl]) + xwo;
                float c = sigmoidf_fast(gf) * cst[t & 1][jl] + sigmoidf_fast(gi) * tanhf_fast(gg);
                float h = sigmoidf_fast(go) * tanhf_fast(c);
                int j = j0 + jl;
                __half hhv = __float2half_rn(h);
                g_hrep[(t + 1) & 1][warp][j] = hhv;           // this warp's copy
                if (warp == 0) {
                    cst[(t + 1) & 1][jl] = c;
                    g_hseq[(size_t)t * H2 + j] = hhv;         // for next layer's GEMM
                    if (last_layer && t == T_STEPS - 1) g_hlast[j] = h;
                }
            }
            asm volatile("bar.sync 1, 256;" ::: "memory");    // warps 0-7: copies done
            if (warp == 0 && lane == 0)
                red_add_release(&g_steps[t * 32]);            // fire-and-forget arrive
        } else if (warp == 8 && lane == 0) {
            const unsigned* cnt = &g_steps[t * 32];           // concurrent waiter
            int spin = 0;
            while ((int)(ld_acq(cnt) - tgt) < 0) { if (++spin > 256) __nanosleep(64); }
        }
        __syncthreads();
    }

    // bump the launch epoch (exactly one thread grid-wide; all CTAs read E at start)
    if (cta0 && tid == 0) st_rlx(&g_epoch, E + 1);
}

// ---------------- final projection + log_softmax ----------------
__global__ void final_kernel(const float* __restrict__ wout, const float* __restrict__ bout,
                             float* __restrict__ out) {
    int tid = threadIdx.x;
    float s0 = 0.f, s1 = 0.f;
    for (int k = tid; k < H2; k += 256) {
        float h = g_hlast[k];
        s0 = fmaf(h, wout[k], s0);
        s1 = fmaf(h, wout[H2 + k], s1);
    }
    __shared__ float r0[8], r1[8];
#pragma unroll
    for (int o = 16; o; o >>= 1) {
        s0 += __shfl_xor_sync(0xffffffffu, s0, o);
        s1 += __shfl_xor_sync(0xffffffffu, s1, o);
    }
    if ((tid & 31) == 0) { r0[tid >> 5] = s0; r1[tid >> 5] = s1; }
    __syncthreads();
    if (tid == 0) {
        float l0 = bout[0], l1 = bout[1];
        for (int w = 0; w < 8; w++) { l0 += r0[w]; l1 += r1[w]; }
        float m = fmaxf(l0, l1);
        float z = expf(l0 - m) + expf(l1 - m);
        float lse = m + logf(z);
        out[0] = l0 - lse;
        out[1] = l1 - lse;
    }
}

// ---------------- launcher ----------------
extern "C" void kernel_launch(void* const* d_in, const int* in_sizes, int n_in,
                              void* d_out, int out_size) {
    const float* event = (const float*)d_in[0];
    const float* w_ih0 = (const float*)d_in[1];   // (8192, 1)
    const float* w_ih  = (const float*)d_in[2];   // (3, 8192, 2048)
    const float* w_hh  = (const float*)d_in[3];   // (4, 8192, 2048)
    const float* b_ih  = (const float*)d_in[4];   // (4, 8192)
    const float* b_hh  = (const float*)d_in[5];   // (4, 8192)
    const float* w_out = (const float*)d_in[6];   // (2, 2048)
    const float* b_out = (const float*)d_in[7];   // (2,)
    float* out = (float*)d_out;

    cudaFuncSetAttribute(lstm_scan, cudaFuncAttributeMaxDynamicSharedMemorySize, SCAN_SMEM);

    // launch order (for ncu -s 5): pack(0), xw0(1), nop(2), scan_l0(3),
    // gemm_l1(4), scan_l1(5) <- profiled, gemm_l2(6), scan_l2(7), ...
    pack_extra<<<dim3(NCTA, LAYERS), 256>>>(w_hh);

    for (int l = 0; l < LAYERS; ++l) {
        if (l == 0) {
            dim3 grid(NG / (256 * 4), T_STEPS);
            xw0_kernel<<<grid, 256>>>(event, w_ih0, b_ih, b_hh);
            nop_kernel<<<1, 1>>>();
        } else {
            dim3 grid(NG / BN, T_STEPS / BM);
            gemm_xw<<<grid, 256>>>(w_ih + (size_t)(l - 1) * NG * H2,
                                   b_ih + (size_t)l * NG,
                                   b_hh + (size_t)l * NG);
        }
        lstm_scan<<<NCTA, SCAN_THREADS, SCAN_SMEM>>>(w_hh + (size_t)l * NG * H2, l);
    }
    final_kernel<<<1, 256>>>(w_out, b_out, out);
}